// round 1
// baseline (speedup 1.0000x reference)
#include <cuda_runtime.h>

#define D_MODEL 512
#define HCOUNT  8
#define DH      64
#define BATCH   4
#define SEQ     2048
#define MTOT    (BATCH * SEQ)   // 8192

// Scratch (allocation-free rule: __device__ globals)
__device__ float g_Q[MTOT * D_MODEL];
__device__ float g_K[MTOT * D_MODEL];
__device__ float g_V[MTOT * D_MODEL];
__device__ float g_Z[MTOT * D_MODEL];

// ---------------------------------------------------------------------------
// GEMM: C[M,512] = A[M,512] @ W[512,512] + bias    (BM=64, BN=64, BK=16)
// 256 threads, 4x4 microtile per thread.
// ---------------------------------------------------------------------------
__global__ __launch_bounds__(256) void gemm_bias_kernel(
    const float* __restrict__ A, const float* __restrict__ W,
    const float* __restrict__ bias, float* __restrict__ C)
{
    __shared__ float As[16][64];   // [k][m] (transposed)
    __shared__ float Bs[16][64];   // [k][n]

    const int tid = threadIdx.x;
    const int tx  = tid & 15;      // 0..15  -> n microtile
    const int ty  = tid >> 4;      // 0..15  -> m microtile
    const int m0  = blockIdx.x * 64;
    const int n0  = blockIdx.y * 64;

    const int lm  = tid >> 2;          // 0..63  A-load row
    const int lk4 = (tid & 3) * 4;     // 0,4,8,12
    const int lbk = tid >> 4;          // 0..15  B-load row
    const int lbn = (tid & 15) * 4;    // 0..60

    float acc[4][4] = {};

    for (int kb = 0; kb < D_MODEL; kb += 16) {
        float4 av = *(const float4*)&A[(size_t)(m0 + lm) * D_MODEL + kb + lk4];
        float4 bv = *(const float4*)&W[(size_t)(kb + lbk) * D_MODEL + n0 + lbn];
        __syncthreads();               // prior-iter reads done
        As[lk4 + 0][lm] = av.x;
        As[lk4 + 1][lm] = av.y;
        As[lk4 + 2][lm] = av.z;
        As[lk4 + 3][lm] = av.w;
        *(float4*)&Bs[lbk][lbn] = bv;
        __syncthreads();
        #pragma unroll
        for (int k = 0; k < 16; k++) {
            float4 a4 = *(const float4*)&As[k][ty * 4];
            float4 b4 = *(const float4*)&Bs[k][tx * 4];
            float aa[4] = {a4.x, a4.y, a4.z, a4.w};
            float bb[4] = {b4.x, b4.y, b4.z, b4.w};
            #pragma unroll
            for (int i = 0; i < 4; i++)
                #pragma unroll
                for (int j = 0; j < 4; j++)
                    acc[i][j] += aa[i] * bb[j];
        }
    }

    float4 bvec = *(const float4*)&bias[n0 + tx * 4];
    const float bb[4] = {bvec.x, bvec.y, bvec.z, bvec.w};
    #pragma unroll
    for (int i = 0; i < 4; i++) {
        float4 r = make_float4(acc[i][0] + bb[0], acc[i][1] + bb[1],
                               acc[i][2] + bb[2], acc[i][3] + bb[3]);
        *(float4*)&C[(size_t)(m0 + ty * 4 + i) * D_MODEL + n0 + tx * 4] = r;
    }
}

// ---------------------------------------------------------------------------
// Flash attention (fp32, online softmax). One block = 64 query rows for one
// (batch, head). BN=64 key tile. 256 threads, 4x4 microtile.
// ---------------------------------------------------------------------------
__global__ __launch_bounds__(256) void attn_kernel(
    const float* __restrict__ Q, const float* __restrict__ K,
    const float* __restrict__ V, float* __restrict__ Z)
{
    __shared__ float Qs [64][64];  // [k][m]  (scaled by 1/8 at load)
    __shared__ float KVs[64][64];  // phase 1: K as [k][n]; phase 2: V as [key][d]
    __shared__ float Ps [64][64];  // [m][key]

    const int tid = threadIdx.x;
    const int tx  = tid & 15;
    const int ty  = tid >> 4;
    const int q0  = blockIdx.x * 64;
    const int bh  = blockIdx.y;                       // b*8 + h
    const int b   = bh >> 3, h = bh & 7;
    const size_t base = (size_t)b * SEQ * D_MODEL + (size_t)h * DH;

    const float SCALE = 0.125f;                       // 1/sqrt(64)
    const float LOG2E = 1.4426950408889634f;

    const int lrowi = tid >> 2;       // 0..63 load row
    const int lf4   = tid & 3;        // float4 group selector

    // --- load Q tile, transpose to [k][m], fold in softmax scale ---
    #pragma unroll
    for (int j = 0; j < 4; j++) {
        const int kk = lf4 * 4 + j * 16;
        float4 v = *(const float4*)&Q[base + (size_t)(q0 + lrowi) * D_MODEL + kk];
        Qs[kk + 0][lrowi] = v.x * SCALE;
        Qs[kk + 1][lrowi] = v.y * SCALE;
        Qs[kk + 2][lrowi] = v.z * SCALE;
        Qs[kk + 3][lrowi] = v.w * SCALE;
    }

    float o[4][4] = {};
    float mrow[4] = {-1e30f, -1e30f, -1e30f, -1e30f};
    float lrow[4] = {};

    for (int t0 = 0; t0 < SEQ; t0 += 64) {
        // ---- load K tile (issue LDG early) ----
        float4 kreg[4];
        #pragma unroll
        for (int j = 0; j < 4; j++) {
            const int kk = lf4 * 4 + j * 16;
            kreg[j] = *(const float4*)&K[base + (size_t)(t0 + lrowi) * D_MODEL + kk];
        }
        __syncthreads();          // prior PV reads of KVs done
        #pragma unroll
        for (int j = 0; j < 4; j++) {
            const int kk = lf4 * 4 + j * 16;
            KVs[kk + 0][lrowi] = kreg[j].x;
            KVs[kk + 1][lrowi] = kreg[j].y;
            KVs[kk + 2][lrowi] = kreg[j].z;
            KVs[kk + 3][lrowi] = kreg[j].w;
        }
        __syncthreads();          // K (and Qs on iter 0) visible

        // ---- S = (Q*scale) @ K^T ----
        float s[4][4] = {};
        #pragma unroll 16
        for (int k = 0; k < 64; k++) {
            float4 a4 = *(const float4*)&Qs[k][ty * 4];
            float4 b4 = *(const float4*)&KVs[k][tx * 4];
            float aa[4] = {a4.x, a4.y, a4.z, a4.w};
            float bb[4] = {b4.x, b4.y, b4.z, b4.w};
            #pragma unroll
            for (int i = 0; i < 4; i++)
                #pragma unroll
                for (int j = 0; j < 4; j++)
                    s[i][j] += aa[i] * bb[j];
        }

        // ---- online softmax (rows shared by 16 lanes of a half-warp) ----
        #pragma unroll
        for (int i = 0; i < 4; i++) {
            float mx = fmaxf(fmaxf(s[i][0], s[i][1]), fmaxf(s[i][2], s[i][3]));
            #pragma unroll
            for (int off = 8; off; off >>= 1)
                mx = fmaxf(mx, __shfl_xor_sync(0xffffffffu, mx, off, 16));
            const float mnew  = fmaxf(mrow[i], mx);
            const float alpha = exp2f((mrow[i] - mnew) * LOG2E);
            mrow[i] = mnew;
            float rs = 0.0f;
            #pragma unroll
            for (int j = 0; j < 4; j++) {
                s[i][j] = exp2f((s[i][j] - mnew) * LOG2E);
                rs += s[i][j];
            }
            #pragma unroll
            for (int off = 8; off; off >>= 1)
                rs += __shfl_xor_sync(0xffffffffu, rs, off, 16);
            lrow[i] = lrow[i] * alpha + rs;
            #pragma unroll
            for (int j = 0; j < 4; j++) o[i][j] *= alpha;
            *(float4*)&Ps[ty * 4 + i][tx * 4] =
                make_float4(s[i][0], s[i][1], s[i][2], s[i][3]);
        }

        // ---- load V tile (natural layout), reusing KVs ----
        float4 vreg[4];
        #pragma unroll
        for (int j = 0; j < 4; j++) {
            const int kk = lf4 * 4 + j * 16;
            vreg[j] = *(const float4*)&V[base + (size_t)(t0 + lrowi) * D_MODEL + kk];
        }
        __syncthreads();          // Ps visible; K reads of KVs done
        #pragma unroll
        for (int j = 0; j < 4; j++) {
            const int kk = lf4 * 4 + j * 16;
            *(float4*)&KVs[lrowi][kk] = vreg[j];
        }
        __syncthreads();          // V visible

        // ---- O += P @ V ----
        #pragma unroll 8
        for (int k = 0; k < 64; k++) {
            const float a0 = Ps[ty * 4 + 0][k];
            const float a1 = Ps[ty * 4 + 1][k];
            const float a2 = Ps[ty * 4 + 2][k];
            const float a3 = Ps[ty * 4 + 3][k];
            float4 b4 = *(const float4*)&KVs[k][tx * 4];
            const float bb[4] = {b4.x, b4.y, b4.z, b4.w};
            #pragma unroll
            for (int j = 0; j < 4; j++) {
                o[0][j] += a0 * bb[j];
                o[1][j] += a1 * bb[j];
                o[2][j] += a2 * bb[j];
                o[3][j] += a3 * bb[j];
            }
        }
    }

    // ---- epilogue: normalize, write Z[b, q, h*64 + d] ----
    #pragma unroll
    for (int i = 0; i < 4; i++) {
        const float inv = 1.0f / lrow[i];
        float4 r = make_float4(o[i][0] * inv, o[i][1] * inv,
                               o[i][2] * inv, o[i][3] * inv);
        *(float4*)&Z[base + (size_t)(q0 + ty * 4 + i) * D_MODEL + tx * 4] = r;
    }
}

// ---------------------------------------------------------------------------
extern "C" void kernel_launch(void* const* d_in, const int* in_sizes, int n_in,
                              void* d_out, int out_size)
{
    const float* x  = (const float*)d_in[0];
    const float* Wq = (const float*)d_in[1];
    const float* bq = (const float*)d_in[2];
    const float* Wk = (const float*)d_in[3];
    const float* bk = (const float*)d_in[4];
    const float* Wv = (const float*)d_in[5];
    const float* bv = (const float*)d_in[6];
    const float* Wo = (const float*)d_in[7];
    const float* bo = (const float*)d_in[8];
    float* out = (float*)d_out;

    float *Qp, *Kp, *Vp, *Zp;
    cudaGetSymbolAddress((void**)&Qp, g_Q);
    cudaGetSymbolAddress((void**)&Kp, g_K);
    cudaGetSymbolAddress((void**)&Vp, g_V);
    cudaGetSymbolAddress((void**)&Zp, g_Z);

    dim3 ggrid(MTOT / 64, D_MODEL / 64);   // (128, 8)
    gemm_bias_kernel<<<ggrid, 256>>>(x, Wq, bq, Qp);
    gemm_bias_kernel<<<ggrid, 256>>>(x, Wk, bk, Kp);
    gemm_bias_kernel<<<ggrid, 256>>>(x, Wv, bv, Vp);

    dim3 agrid(SEQ / 64, BATCH * HCOUNT);  // (32, 32)
    attn_kernel<<<agrid, 256>>>(Qp, Kp, Vp, Zp);

    gemm_bias_kernel<<<ggrid, 256>>>(Zp, Wo, bo, out);
}

// round 2
// speedup vs baseline: 1.3246x; 1.3246x over previous
#include <cuda_runtime.h>
#include <cstdint>

#define D_MODEL 512
#define HCOUNT  8
#define DH      64
#define BATCH   4
#define SEQ     2048
#define MTOT    (BATCH * SEQ)   // 8192

// Scratch (allocation-free rule: __device__ globals)
__device__ float g_Q[MTOT * D_MODEL];
__device__ float g_K[MTOT * D_MODEL];
__device__ float g_V[MTOT * D_MODEL];
__device__ float g_Z[MTOT * D_MODEL];

// ---------------------------------------------------------------------------
// helpers
// ---------------------------------------------------------------------------
__device__ __forceinline__ uint32_t f2tf32(float x) {
    uint32_t u;
    asm("cvt.rna.tf32.f32 %0, %1;" : "=r"(u) : "f"(x));
    return u;
}

__device__ __forceinline__ void mma_tf32(float* d, const uint32_t* a,
                                         uint32_t b0, uint32_t b1) {
    asm volatile(
        "mma.sync.aligned.m16n8k8.row.col.f32.tf32.tf32.f32 "
        "{%0,%1,%2,%3}, {%4,%5,%6,%7}, {%8,%9}, {%0,%1,%2,%3};\n"
        : "+f"(d[0]), "+f"(d[1]), "+f"(d[2]), "+f"(d[3])
        : "r"(a[0]), "r"(a[1]), "r"(a[2]), "r"(a[3]), "r"(b0), "r"(b1));
}

// ---------------------------------------------------------------------------
// GEMM: C[M,512] = A[M,512] @ W[512,512] + bias    (BM=64, BN=64, BK=16)
// 256 threads, 4x4 microtile per thread. (fp32 exact; at FFMA roofline)
// ---------------------------------------------------------------------------
__global__ __launch_bounds__(256) void gemm_bias_kernel(
    const float* __restrict__ A, const float* __restrict__ W,
    const float* __restrict__ bias, float* __restrict__ C)
{
    __shared__ float As[16][64];   // [k][m] (transposed)
    __shared__ float Bs[16][64];   // [k][n]

    const int tid = threadIdx.x;
    const int tx  = tid & 15;
    const int ty  = tid >> 4;
    const int m0  = blockIdx.x * 64;
    const int n0  = blockIdx.y * 64;

    const int lm  = tid >> 2;
    const int lk4 = (tid & 3) * 4;
    const int lbk = tid >> 4;
    const int lbn = (tid & 15) * 4;

    float acc[4][4] = {};

    for (int kb = 0; kb < D_MODEL; kb += 16) {
        float4 av = *(const float4*)&A[(size_t)(m0 + lm) * D_MODEL + kb + lk4];
        float4 bv = *(const float4*)&W[(size_t)(kb + lbk) * D_MODEL + n0 + lbn];
        __syncthreads();
        As[lk4 + 0][lm] = av.x;
        As[lk4 + 1][lm] = av.y;
        As[lk4 + 2][lm] = av.z;
        As[lk4 + 3][lm] = av.w;
        *(float4*)&Bs[lbk][lbn] = bv;
        __syncthreads();
        #pragma unroll
        for (int k = 0; k < 16; k++) {
            float4 a4 = *(const float4*)&As[k][ty * 4];
            float4 b4 = *(const float4*)&Bs[k][tx * 4];
            float aa[4] = {a4.x, a4.y, a4.z, a4.w};
            float bb[4] = {b4.x, b4.y, b4.z, b4.w};
            #pragma unroll
            for (int i = 0; i < 4; i++)
                #pragma unroll
                for (int j = 0; j < 4; j++)
                    acc[i][j] += aa[i] * bb[j];
        }
    }

    float4 bvec = *(const float4*)&bias[n0 + tx * 4];
    const float bb[4] = {bvec.x, bvec.y, bvec.z, bvec.w};
    #pragma unroll
    for (int i = 0; i < 4; i++) {
        float4 r = make_float4(acc[i][0] + bb[0], acc[i][1] + bb[1],
                               acc[i][2] + bb[2], acc[i][3] + bb[3]);
        *(float4*)&C[(size_t)(m0 + ty * 4 + i) * D_MODEL + n0 + tx * 4] = r;
    }
}

// ---------------------------------------------------------------------------
// Flash attention, tf32 tensor-core version.
// Block = 64 query rows x one (b,h). 128 threads = 4 warps; each warp owns
// 16 query rows. Key loop in tiles of 64.
//   S = Q@K^T via mma.m16n8k8 tf32 (Q,K rounded RNA; scale+log2e folded in Q)
//   P@V via 2-pass tf32 (V split hi/lo in registers) for accuracy.
// smem strides: Ps 68 (Q-staging / P), KV 68 (K phase) / 72 (V phase)
// -> conflict-free fragment LDS for all access patterns.
// ---------------------------------------------------------------------------
__global__ __launch_bounds__(128) void attn_mma_kernel(
    const float* __restrict__ Q, const float* __restrict__ K,
    const float* __restrict__ V, float* __restrict__ Z)
{
    __shared__ float Ps[64 * 68];   // Q staging, then P tiles
    __shared__ float KV[64 * 72];   // K phase (stride 68), V phase (stride 72)

    const int tid  = threadIdx.x;
    const int lane = tid & 31;
    const int warp = tid >> 5;
    const int r = lane >> 2;        // fragment row-in-group
    const int c = lane & 3;         // fragment col-in-group
    const int wrow = warp * 16;     // warp's first query row (local)

    const int q0 = blockIdx.x * 64;
    const int bh = blockIdx.y;
    const int b  = bh >> 3, h = bh & 7;
    const size_t base = (size_t)b * SEQ * D_MODEL + (size_t)h * DH;

    const float QSCALE = 0.125f * 1.4426950408889634f;  // 1/sqrt(64) * log2(e)

    const int srow = tid >> 1;          // staging row 0..63
    const int scol = (tid & 1) * 32;    // staging col half

    // ---- stage Q (scaled, tf32-RNA) into Ps, then pick up A-fragments ----
    {
        const float* qp = Q + base + (size_t)(q0 + srow) * D_MODEL + scol;
        float* dst = Ps + srow * 68 + scol;
        #pragma unroll
        for (int i = 0; i < 8; i++) {
            float4 v = *(const float4*)(qp + i * 4);
            dst[i*4+0] = __uint_as_float(f2tf32(v.x * QSCALE));
            dst[i*4+1] = __uint_as_float(f2tf32(v.y * QSCALE));
            dst[i*4+2] = __uint_as_float(f2tf32(v.z * QSCALE));
            dst[i*4+3] = __uint_as_float(f2tf32(v.w * QSCALE));
        }
    }
    __syncthreads();

    uint32_t qf[8][4];
    #pragma unroll
    for (int kc = 0; kc < 8; kc++) {
        qf[kc][0] = __float_as_uint(Ps[(wrow + r    ) * 68 + kc*8 + c    ]);
        qf[kc][1] = __float_as_uint(Ps[(wrow + r + 8) * 68 + kc*8 + c    ]);
        qf[kc][2] = __float_as_uint(Ps[(wrow + r    ) * 68 + kc*8 + c + 4]);
        qf[kc][3] = __float_as_uint(Ps[(wrow + r + 8) * 68 + kc*8 + c + 4]);
    }
    __syncthreads();   // Ps now free for P tiles

    float o[8][4] = {};                 // O accum, D-layout, 8 d-tiles
    float mA = -1e30f, mB = -1e30f;     // row maxes (row r / row r+8)
    float lA = 0.0f,   lB = 0.0f;       // row sums

    for (int t0 = 0; t0 < SEQ; t0 += 64) {
        // ---- load K tile to registers (early LDG) ----
        float4 kreg[8];
        {
            const float* kp = K + base + (size_t)(t0 + srow) * D_MODEL + scol;
            #pragma unroll
            for (int i = 0; i < 8; i++) kreg[i] = *(const float4*)(kp + i * 4);
        }
        __syncthreads();                 // previous PV reads of KV done
        {
            float* dst = KV + srow * 68 + scol;   // K layout [key][dim], stride 68
            #pragma unroll
            for (int i = 0; i < 8; i++) {
                dst[i*4+0] = __uint_as_float(f2tf32(kreg[i].x));
                dst[i*4+1] = __uint_as_float(f2tf32(kreg[i].y));
                dst[i*4+2] = __uint_as_float(f2tf32(kreg[i].z));
                dst[i*4+3] = __uint_as_float(f2tf32(kreg[i].w));
            }
        }
        __syncthreads();

        // ---- S = Q @ K^T  (per-warp 16x64) ----
        float s[8][4] = {};
        #pragma unroll
        for (int nt = 0; nt < 8; nt++) {
            #pragma unroll
            for (int kc = 0; kc < 8; kc++) {
                uint32_t b0 = __float_as_uint(KV[(nt*8 + r) * 68 + kc*8 + c    ]);
                uint32_t b1 = __float_as_uint(KV[(nt*8 + r) * 68 + kc*8 + c + 4]);
                mma_tf32(s[nt], qf[kc], b0, b1);
            }
        }

        // ---- online softmax (exp2 domain; rows shared by 4 lanes) ----
        float mxA = s[0][0], mxB = s[0][2];
        #pragma unroll
        for (int nt = 0; nt < 8; nt++) {
            mxA = fmaxf(mxA, fmaxf(s[nt][0], s[nt][1]));
            mxB = fmaxf(mxB, fmaxf(s[nt][2], s[nt][3]));
        }
        mxA = fmaxf(mxA, __shfl_xor_sync(0xffffffffu, mxA, 1));
        mxA = fmaxf(mxA, __shfl_xor_sync(0xffffffffu, mxA, 2));
        mxB = fmaxf(mxB, __shfl_xor_sync(0xffffffffu, mxB, 1));
        mxB = fmaxf(mxB, __shfl_xor_sync(0xffffffffu, mxB, 2));

        const float mnA = fmaxf(mA, mxA);
        const float mnB = fmaxf(mB, mxB);
        const float aA  = exp2f(mA - mnA);
        const float aB  = exp2f(mB - mnB);
        mA = mnA; mB = mnB;

        float sumA = 0.0f, sumB = 0.0f;
        #pragma unroll
        for (int nt = 0; nt < 8; nt++) {
            s[nt][0] = exp2f(s[nt][0] - mnA);
            s[nt][1] = exp2f(s[nt][1] - mnA);
            s[nt][2] = exp2f(s[nt][2] - mnB);
            s[nt][3] = exp2f(s[nt][3] - mnB);
            sumA += s[nt][0] + s[nt][1];
            sumB += s[nt][2] + s[nt][3];
        }
        sumA += __shfl_xor_sync(0xffffffffu, sumA, 1);
        sumA += __shfl_xor_sync(0xffffffffu, sumA, 2);
        sumB += __shfl_xor_sync(0xffffffffu, sumB, 1);
        sumB += __shfl_xor_sync(0xffffffffu, sumB, 2);
        lA = lA * aA + sumA;
        lB = lB * aB + sumB;

        #pragma unroll
        for (int dt = 0; dt < 8; dt++) {
            o[dt][0] *= aA; o[dt][1] *= aA;
            o[dt][2] *= aB; o[dt][3] *= aB;
        }

        // ---- write P (RNA-rounded) into Ps, D-layout -> row-major ----
        #pragma unroll
        for (int nt = 0; nt < 8; nt++) {
            float2 pa = make_float2(__uint_as_float(f2tf32(s[nt][0])),
                                    __uint_as_float(f2tf32(s[nt][1])));
            float2 pb = make_float2(__uint_as_float(f2tf32(s[nt][2])),
                                    __uint_as_float(f2tf32(s[nt][3])));
            *(float2*)&Ps[(wrow + r    ) * 68 + nt*8 + 2*c] = pa;
            *(float2*)&Ps[(wrow + r + 8) * 68 + nt*8 + 2*c] = pb;
        }

        // ---- load V tile (raw fp32) ----
        float4 vreg[8];
        {
            const float* vp = V + base + (size_t)(t0 + srow) * D_MODEL + scol;
            #pragma unroll
            for (int i = 0; i < 8; i++) vreg[i] = *(const float4*)(vp + i * 4);
        }
        __syncthreads();                 // S-phase KV reads done; P visible
        {
            float* dst = KV + srow * 72 + scol;   // V layout [key][d], stride 72
            #pragma unroll
            for (int i = 0; i < 8; i++)
                *(float4*)(dst + i * 4) = vreg[i];
        }
        __syncthreads();

        // ---- O += P @ V  (V split hi/lo in registers, 2 MMA passes) ----
        #pragma unroll
        for (int kc = 0; kc < 8; kc++) {
            uint32_t pf[4];
            pf[0] = __float_as_uint(Ps[(wrow + r    ) * 68 + kc*8 + c    ]);
            pf[1] = __float_as_uint(Ps[(wrow + r + 8) * 68 + kc*8 + c    ]);
            pf[2] = __float_as_uint(Ps[(wrow + r    ) * 68 + kc*8 + c + 4]);
            pf[3] = __float_as_uint(Ps[(wrow + r + 8) * 68 + kc*8 + c + 4]);
            #pragma unroll
            for (int dt = 0; dt < 8; dt++) {
                float v0 = KV[(kc*8 + c    ) * 72 + dt*8 + r];
                float v1 = KV[(kc*8 + c + 4) * 72 + dt*8 + r];
                uint32_t h0 = f2tf32(v0);
                uint32_t h1 = f2tf32(v1);
                uint32_t l0 = f2tf32(v0 - __uint_as_float(h0));
                uint32_t l1 = f2tf32(v1 - __uint_as_float(h1));
                mma_tf32(o[dt], pf, h0, h1);
                mma_tf32(o[dt], pf, l0, l1);
            }
        }
    }

    // ---- epilogue: normalize and store Z ----
    const float iA = 1.0f / lA;
    const float iB = 1.0f / lB;
    #pragma unroll
    for (int dt = 0; dt < 8; dt++) {
        float2 za = make_float2(o[dt][0] * iA, o[dt][1] * iA);
        float2 zb = make_float2(o[dt][2] * iB, o[dt][3] * iB);
        *(float2*)&Z[base + (size_t)(q0 + wrow + r    ) * D_MODEL + dt*8 + 2*c] = za;
        *(float2*)&Z[base + (size_t)(q0 + wrow + r + 8) * D_MODEL + dt*8 + 2*c] = zb;
    }
}

// ---------------------------------------------------------------------------
extern "C" void kernel_launch(void* const* d_in, const int* in_sizes, int n_in,
                              void* d_out, int out_size)
{
    const float* x  = (const float*)d_in[0];
    const float* Wq = (const float*)d_in[1];
    const float* bq = (const float*)d_in[2];
    const float* Wk = (const float*)d_in[3];
    const float* bk = (const float*)d_in[4];
    const float* Wv = (const float*)d_in[5];
    const float* bv = (const float*)d_in[6];
    const float* Wo = (const float*)d_in[7];
    const float* bo = (const float*)d_in[8];
    float* out = (float*)d_out;

    float *Qp, *Kp, *Vp, *Zp;
    cudaGetSymbolAddress((void**)&Qp, g_Q);
    cudaGetSymbolAddress((void**)&Kp, g_K);
    cudaGetSymbolAddress((void**)&Vp, g_V);
    cudaGetSymbolAddress((void**)&Zp, g_Z);

    dim3 ggrid(MTOT / 64, D_MODEL / 64);   // (128, 8)
    gemm_bias_kernel<<<ggrid, 256>>>(x, Wq, bq, Qp);
    gemm_bias_kernel<<<ggrid, 256>>>(x, Wk, bk, Kp);
    gemm_bias_kernel<<<ggrid, 256>>>(x, Wv, bv, Vp);

    dim3 agrid(SEQ / 64, BATCH * HCOUNT);  // (32, 32)
    attn_mma_kernel<<<agrid, 128>>>(Qp, Kp, Vp, Zp);

    gemm_bias_kernel<<<ggrid, 256>>>(Zp, Wo, bo, out);
}

// round 4
// speedup vs baseline: 2.0155x; 1.5216x over previous
#include <cuda_runtime.h>
#include <cstdint>

#define D_MODEL 512
#define HCOUNT  8
#define DH      64
#define BATCH   4
#define SEQ     2048
#define MTOT    (BATCH * SEQ)   // 8192

// Scratch (allocation-free rule: __device__ globals)
__device__ float g_Q[MTOT * D_MODEL];
__device__ float g_K[MTOT * D_MODEL];
__device__ float g_V[MTOT * D_MODEL];
__device__ float g_Z[MTOT * D_MODEL];

// ---------------------------------------------------------------------------
// helpers
// ---------------------------------------------------------------------------
__device__ __forceinline__ uint32_t f2tf32(float x) {
    uint32_t u;
    asm("cvt.rna.tf32.f32 %0, %1;" : "=r"(u) : "f"(x));
    return u;
}
__device__ __forceinline__ float ex2(float x) {
    float y;
    asm("ex2.approx.f32 %0, %1;" : "=f"(y) : "f"(x));
    return y;
}
__device__ __forceinline__ void mma_tf32(float* d, const uint32_t* a,
                                         uint32_t b0, uint32_t b1) {
    asm volatile(
        "mma.sync.aligned.m16n8k8.row.col.f32.tf32.tf32.f32 "
        "{%0,%1,%2,%3}, {%4,%5,%6,%7}, {%8,%9}, {%0,%1,%2,%3};\n"
        : "+f"(d[0]), "+f"(d[1]), "+f"(d[2]), "+f"(d[3])
        : "r"(a[0]), "r"(a[1]), "r"(a[2]), "r"(a[3]), "r"(b0), "r"(b1));
}
__device__ __forceinline__ void cp16(uint32_t dst, const void* src) {
    asm volatile("cp.async.ca.shared.global [%0], [%1], 16;"
                 :: "r"(dst), "l"(src));
}
__device__ __forceinline__ uint32_t smem_u32(const void* p) {
    return (uint32_t)__cvta_generic_to_shared(p);
}

// ---------------------------------------------------------------------------
// tf32 GEMM: C[M,512] = A[M,512] @ W[512,512] + bias
// BM=128, BN=64, BK=16; 256 threads = 8 warps (4m x 2n), warp tile 32x32.
// cp.async double-buffered; operands cvt.rna'd in registers after LDS.
// Strides: As 20, Ws 72 -> conflict-free fragment LDS.
// ---------------------------------------------------------------------------
__global__ __launch_bounds__(256) void gemm_tf32_kernel(
    const float* __restrict__ A, const float* __restrict__ W,
    const float* __restrict__ bias, float* __restrict__ C)
{
    __shared__ float As[2][128 * 20];
    __shared__ float Ws[2][16 * 72];

    const int tid  = threadIdx.x;
    const int lane = tid & 31;
    const int warp = tid >> 5;
    const int r = lane >> 2;
    const int c = lane & 3;
    const int wmb = (warp >> 1) * 32;
    const int wnb = (warp & 1) * 32;
    const int m0 = blockIdx.x * 128;
    const int n0 = blockIdx.y * 64;

    // cp.async mappings
    const int arow = tid >> 1;             // 0..127  (A rows)
    const int aoff = (tid & 1) * 2;        // float4 pair 0/1 or 2/3
    const int wrr  = tid >> 4;             // 0..15   (W rows)
    const int wcc  = (tid & 15) * 4;       // 0..60   (W cols, float4)

    float acc[2][4][4] = {};

    auto load_stage = [&](int s, int kb) {
        cp16(smem_u32(&As[s][arow * 20 + aoff * 4]),
             &A[(size_t)(m0 + arow) * D_MODEL + kb + aoff * 4]);
        cp16(smem_u32(&As[s][arow * 20 + (aoff + 1) * 4]),
             &A[(size_t)(m0 + arow) * D_MODEL + kb + (aoff + 1) * 4]);
        cp16(smem_u32(&Ws[s][wrr * 72 + wcc]),
             &W[(size_t)(kb + wrr) * D_MODEL + n0 + wcc]);
        asm volatile("cp.async.commit_group;");
    };

    load_stage(0, 0);

    for (int it = 0; it < D_MODEL / 16; ++it) {
        const int s = it & 1;
        if (it + 1 < D_MODEL / 16) {
            load_stage(s ^ 1, (it + 1) * 16);
            asm volatile("cp.async.wait_group 1;");
        } else {
            asm volatile("cp.async.wait_group 0;");
        }
        __syncthreads();

        uint32_t af[2][2][4];
        uint32_t bf[4][2][2];
        #pragma unroll
        for (int mt = 0; mt < 2; mt++)
            #pragma unroll
            for (int kc = 0; kc < 2; kc++) {
                const int row = wmb + mt * 16;
                af[mt][kc][0] = f2tf32(As[s][(row + r    ) * 20 + kc * 8 + c    ]);
                af[mt][kc][1] = f2tf32(As[s][(row + r + 8) * 20 + kc * 8 + c    ]);
                af[mt][kc][2] = f2tf32(As[s][(row + r    ) * 20 + kc * 8 + c + 4]);
                af[mt][kc][3] = f2tf32(As[s][(row + r + 8) * 20 + kc * 8 + c + 4]);
            }
        #pragma unroll
        for (int nt = 0; nt < 4; nt++)
            #pragma unroll
            for (int kc = 0; kc < 2; kc++) {
                bf[nt][kc][0] = f2tf32(Ws[s][(kc * 8 + c    ) * 72 + wnb + nt * 8 + r]);
                bf[nt][kc][1] = f2tf32(Ws[s][(kc * 8 + c + 4) * 72 + wnb + nt * 8 + r]);
            }
        #pragma unroll
        for (int mt = 0; mt < 2; mt++)
            #pragma unroll
            for (int nt = 0; nt < 4; nt++)
                #pragma unroll
                for (int kc = 0; kc < 2; kc++)
                    mma_tf32(acc[mt][nt], af[mt][kc], bf[nt][kc][0], bf[nt][kc][1]);
        __syncthreads();
    }

    // epilogue: bias + store (float2 per fragment row)
    #pragma unroll
    for (int mt = 0; mt < 2; mt++) {
        #pragma unroll
        for (int nt = 0; nt < 4; nt++) {
            const int col = n0 + wnb + nt * 8 + 2 * c;
            const float b0 = bias[col], b1 = bias[col + 1];
            const int row0 = m0 + wmb + mt * 16 + r;
            *(float2*)&C[(size_t)row0 * D_MODEL + col] =
                make_float2(acc[mt][nt][0] + b0, acc[mt][nt][1] + b1);
            *(float2*)&C[(size_t)(row0 + 8) * D_MODEL + col] =
                make_float2(acc[mt][nt][2] + b0, acc[mt][nt][3] + b1);
        }
    }
}

// ---------------------------------------------------------------------------
// Flash attention tf32 v2.
// Block = 64 q-rows x one (b,h); 128 threads = 4 warps x 16 q-rows.
//  - K smem [key][dim perm-paired] stride 72: B-frags via 1 conflict-free LDS.64
//  - V smem [key][dim] stride 72, single tf32-rounded (no hi/lo split)
//  - P stays in registers: C-frag -> A-frag via 8 shuffles per 16x8 tile
//  - 2 syncthreads per key tile
// ---------------------------------------------------------------------------
__global__ __launch_bounds__(128) void attn_mma_kernel(
    const float* __restrict__ Q, const float* __restrict__ K,
    const float* __restrict__ V, float* __restrict__ Z)
{
    __shared__ float Ks[64 * 72];
    __shared__ float Vs[64 * 72];

    const int tid  = threadIdx.x;
    const int lane = tid & 31;
    const int warp = tid >> 5;
    const int r = lane >> 2;
    const int c = lane & 3;
    const int wrow = warp * 16;

    const int q0 = blockIdx.x * 64;
    const int bh = blockIdx.y;
    const int b  = bh >> 3, h = bh & 7;
    const size_t base = (size_t)b * SEQ * D_MODEL + (size_t)h * DH;

    const float QSCALE = 0.125f * 1.4426950408889634f;  // 1/sqrt(64) * log2(e)

    const int srow = tid >> 1;          // 0..63
    const int scol = (tid & 1) * 32;    // dim half
    const int sg   = (tid & 1) * 4;     // first kc group of this thread

    // ---- stage Q into Ks (perm-pair layout), gather A-fragments ----
    {
        const float* qp = Q + base + (size_t)(q0 + srow) * D_MODEL + scol;
        #pragma unroll
        for (int g = 0; g < 4; g++) {               // kc groups
            float4 fa = *(const float4*)(qp + g * 8);
            float4 fb = *(const float4*)(qp + g * 8 + 4);
            float* dst = &Ks[srow * 72 + (sg + g) * 8];
            ((float2*)dst)[0] = make_float2(__uint_as_float(f2tf32(fa.x * QSCALE)),
                                            __uint_as_float(f2tf32(fb.x * QSCALE)));
            ((float2*)dst)[1] = make_float2(__uint_as_float(f2tf32(fa.y * QSCALE)),
                                            __uint_as_float(f2tf32(fb.y * QSCALE)));
            ((float2*)dst)[2] = make_float2(__uint_as_float(f2tf32(fa.z * QSCALE)),
                                            __uint_as_float(f2tf32(fb.z * QSCALE)));
            ((float2*)dst)[3] = make_float2(__uint_as_float(f2tf32(fa.w * QSCALE)),
                                            __uint_as_float(f2tf32(fb.w * QSCALE)));
        }
    }
    __syncthreads();

    uint32_t qf[8][4];
    #pragma unroll
    for (int kc = 0; kc < 8; kc++) {
        float2 pa = *(const float2*)&Ks[(wrow + r    ) * 72 + kc * 8 + 2 * c];
        float2 pb = *(const float2*)&Ks[(wrow + r + 8) * 72 + kc * 8 + 2 * c];
        qf[kc][0] = __float_as_uint(pa.x);
        qf[kc][1] = __float_as_uint(pb.x);
        qf[kc][2] = __float_as_uint(pa.y);
        qf[kc][3] = __float_as_uint(pb.y);
    }
    __syncthreads();   // Ks free for K tiles

    float o[8][4] = {};
    float mA = -1e30f, mB = -1e30f;
    float lA = 0.0f,   lB = 0.0f;

    for (int t0 = 0; t0 < SEQ; t0 += 64) {
        // ---- load K tile, store perm-pair cvt'd ----
        {
            const float* kp = K + base + (size_t)(t0 + srow) * D_MODEL + scol;
            float4 ka[4], kb[4];
            #pragma unroll
            for (int g = 0; g < 4; g++) {
                ka[g] = *(const float4*)(kp + g * 8);
                kb[g] = *(const float4*)(kp + g * 8 + 4);
            }
            #pragma unroll
            for (int g = 0; g < 4; g++) {
                float* dst = &Ks[srow * 72 + (sg + g) * 8];
                ((float2*)dst)[0] = make_float2(__uint_as_float(f2tf32(ka[g].x)),
                                                __uint_as_float(f2tf32(kb[g].x)));
                ((float2*)dst)[1] = make_float2(__uint_as_float(f2tf32(ka[g].y)),
                                                __uint_as_float(f2tf32(kb[g].y)));
                ((float2*)dst)[2] = make_float2(__uint_as_float(f2tf32(ka[g].z)),
                                                __uint_as_float(f2tf32(kb[g].z)));
                ((float2*)dst)[3] = make_float2(__uint_as_float(f2tf32(ka[g].w)),
                                                __uint_as_float(f2tf32(kb[g].w)));
            }
        }
        __syncthreads();   // K visible; prev PV reads of Vs complete

        const float* vp = V + base + (size_t)(t0 + srow) * D_MODEL + scol;
        float4 vrA[4];
        #pragma unroll
        for (int i = 0; i < 4; i++) vrA[i] = *(const float4*)(vp + i * 4);

        // ---- S = Q @ K^T ----
        float s[8][4] = {};
        #pragma unroll
        for (int nt = 0; nt < 4; nt++) {
            #pragma unroll
            for (int kc = 0; kc < 8; kc++) {
                float2 kk = *(const float2*)&Ks[(nt * 8 + r) * 72 + kc * 8 + 2 * c];
                mma_tf32(s[nt], qf[kc], __float_as_uint(kk.x), __float_as_uint(kk.y));
            }
        }
        float4 vrB[4];
        #pragma unroll
        for (int i = 0; i < 4; i++) vrB[i] = *(const float4*)(vp + 16 + i * 4);
        #pragma unroll
        for (int nt = 4; nt < 8; nt++) {
            #pragma unroll
            for (int kc = 0; kc < 8; kc++) {
                float2 kk = *(const float2*)&Ks[(nt * 8 + r) * 72 + kc * 8 + 2 * c];
                mma_tf32(s[nt], qf[kc], __float_as_uint(kk.x), __float_as_uint(kk.y));
            }
        }

        // ---- online softmax (log2 domain; scale folded into Q) ----
        float mxA = s[0][0], mxB = s[0][2];
        #pragma unroll
        for (int nt = 0; nt < 8; nt++) {
            mxA = fmaxf(mxA, fmaxf(s[nt][0], s[nt][1]));
            mxB = fmaxf(mxB, fmaxf(s[nt][2], s[nt][3]));
        }
        mxA = fmaxf(mxA, __shfl_xor_sync(0xffffffffu, mxA, 1));
        mxA = fmaxf(mxA, __shfl_xor_sync(0xffffffffu, mxA, 2));
        mxB = fmaxf(mxB, __shfl_xor_sync(0xffffffffu, mxB, 1));
        mxB = fmaxf(mxB, __shfl_xor_sync(0xffffffffu, mxB, 2));

        const float mnA = fmaxf(mA, mxA);
        const float mnB = fmaxf(mB, mxB);
        const float aA  = ex2(mA - mnA);
        const float aB  = ex2(mB - mnB);
        mA = mnA; mB = mnB;

        float sumA = 0.0f, sumB = 0.0f;
        #pragma unroll
        for (int nt = 0; nt < 8; nt++) {
            s[nt][0] = ex2(s[nt][0] - mnA);
            s[nt][1] = ex2(s[nt][1] - mnA);
            s[nt][2] = ex2(s[nt][2] - mnB);
            s[nt][3] = ex2(s[nt][3] - mnB);
            sumA += s[nt][0] + s[nt][1];
            sumB += s[nt][2] + s[nt][3];
        }
        sumA += __shfl_xor_sync(0xffffffffu, sumA, 1);
        sumA += __shfl_xor_sync(0xffffffffu, sumA, 2);
        sumB += __shfl_xor_sync(0xffffffffu, sumB, 1);
        sumB += __shfl_xor_sync(0xffffffffu, sumB, 2);
        lA = lA * aA + sumA;
        lB = lB * aB + sumB;

        #pragma unroll
        for (int dt = 0; dt < 8; dt++) {
            o[dt][0] *= aA; o[dt][1] *= aA;
            o[dt][2] *= aB; o[dt][3] *= aB;
        }

        // ---- store V tile (cvt.rna, natural layout) ----
        {
            float* dst = &Vs[srow * 72 + scol];
            #pragma unroll
            for (int i = 0; i < 4; i++) {
                *(float4*)(dst + i * 4) = make_float4(
                    __uint_as_float(f2tf32(vrA[i].x)), __uint_as_float(f2tf32(vrA[i].y)),
                    __uint_as_float(f2tf32(vrA[i].z)), __uint_as_float(f2tf32(vrA[i].w)));
                *(float4*)(dst + 16 + i * 4) = make_float4(
                    __uint_as_float(f2tf32(vrB[i].x)), __uint_as_float(f2tf32(vrB[i].y)),
                    __uint_as_float(f2tf32(vrB[i].z)), __uint_as_float(f2tf32(vrB[i].w)));
            }
        }
        __syncthreads();   // V visible; all warps past S-phase K reads

        // ---- O += P @ V : in-register C->A fragment conversion + mma ----
        const int srcA = (lane & 28) | (c >> 1);
        const bool odd = (c & 1);
        #pragma unroll
        for (int kc = 0; kc < 8; kc++) {
            uint32_t p0 = f2tf32(s[kc][0]), p1 = f2tf32(s[kc][1]);
            uint32_t p2 = f2tf32(s[kc][2]), p3 = f2tf32(s[kc][3]);
            uint32_t a0 = __shfl_sync(0xffffffffu, p0, srcA);
            uint32_t a1 = __shfl_sync(0xffffffffu, p1, srcA);
            uint32_t a2 = __shfl_sync(0xffffffffu, p2, srcA);
            uint32_t a3 = __shfl_sync(0xffffffffu, p3, srcA);
            uint32_t b0 = __shfl_sync(0xffffffffu, p0, srcA + 2);
            uint32_t b1 = __shfl_sync(0xffffffffu, p1, srcA + 2);
            uint32_t b2 = __shfl_sync(0xffffffffu, p2, srcA + 2);
            uint32_t b3 = __shfl_sync(0xffffffffu, p3, srcA + 2);
            uint32_t pf[4];
            pf[0] = odd ? a1 : a0;   // P(r,   c)
            pf[1] = odd ? a3 : a2;   // P(r+8, c)
            pf[2] = odd ? b1 : b0;   // P(r,   c+4)
            pf[3] = odd ? b3 : b2;   // P(r+8, c+4)
            #pragma unroll
            for (int dt = 0; dt < 8; dt++) {
                uint32_t v0 = __float_as_uint(Vs[(kc * 8 + c    ) * 72 + dt * 8 + r]);
                uint32_t v1 = __float_as_uint(Vs[(kc * 8 + c + 4) * 72 + dt * 8 + r]);
                mma_tf32(o[dt], pf, v0, v1);
            }
        }
    }

    // ---- epilogue ----
    const float iA = 1.0f / lA;
    const float iB = 1.0f / lB;
    #pragma unroll
    for (int dt = 0; dt < 8; dt++) {
        *(float2*)&Z[base + (size_t)(q0 + wrow + r    ) * D_MODEL + dt * 8 + 2 * c] =
            make_float2(o[dt][0] * iA, o[dt][1] * iA);
        *(float2*)&Z[base + (size_t)(q0 + wrow + r + 8) * D_MODEL + dt * 8 + 2 * c] =
            make_float2(o[dt][2] * iB, o[dt][3] * iB);
    }
}

// ---------------------------------------------------------------------------
extern "C" void kernel_launch(void* const* d_in, const int* in_sizes, int n_in,
                              void* d_out, int out_size)
{
    const float* x  = (const float*)d_in[0];
    const float* Wq = (const float*)d_in[1];
    const float* bq = (const float*)d_in[2];
    const float* Wk = (const float*)d_in[3];
    const float* bk = (const float*)d_in[4];
    const float* Wv = (const float*)d_in[5];
    const float* bv = (const float*)d_in[6];
    const float* Wo = (const float*)d_in[7];
    const float* bo = (const float*)d_in[8];
    float* out = (float*)d_out;

    float *Qp, *Kp, *Vp, *Zp;
    cudaGetSymbolAddress((void**)&Qp, g_Q);
    cudaGetSymbolAddress((void**)&Kp, g_K);
    cudaGetSymbolAddress((void**)&Vp, g_V);
    cudaGetSymbolAddress((void**)&Zp, g_Z);

    dim3 ggrid(MTOT / 128, D_MODEL / 64);   // (64, 8)
    gemm_tf32_kernel<<<ggrid, 256>>>(x, Wq, bq, Qp);
    gemm_tf32_kernel<<<ggrid, 256>>>(x, Wk, bk, Kp);
    gemm_tf32_kernel<<<ggrid, 256>>>(x, Wv, bv, Vp);

    dim3 agrid(SEQ / 64, BATCH * HCOUNT);   // (32, 32)
    attn_mma_kernel<<<agrid, 128>>>(Qp, Kp, Vp, Zp);

    gemm_tf32_kernel<<<ggrid, 256>>>(Zp, Wo, bo, out);
}